// round 8
// baseline (speedup 1.0000x reference)
#include <cuda_runtime.h>
#include <cuda_bf16.h>
#include <cstdint>

// Problem constants (fixed by the reference)
#define BB      16
#define SS      512
#define NH      8
#define MB      4096
#define KBLK    5                       // 2*W+1
#define MRANGE  32                      // rows per slab -> 32*2KB = 64KB? no: 32*512*4 = 64KB
#define SPB     (MB / MRANGE)           // 128 slabs per (b,k) block
#define NSLAB   (BB * KBLK * SPB)       // 10240
#define SLAB_BYTES (MRANGE * SS * 4)    // 65536
#define THREADS 512
#define NCTA    592                     // 148 SMs * 4 resident CTAs

__device__ int g_ctr;

__global__ void reset_ctr_kernel() { g_ctr = 0; }

// Persistent work-stealing CTAs. Each CTA zeroes a 64KB smem buffer ONCE,
// then per stolen slab: issue one cp.async.bulk (smem->global, 64KB),
// wait, barrier, patch nonzeros with plain STG (lines are L2-hot).
__global__ void __launch_bounds__(THREADS) bloom_tma_kernel(
        const int* __restrict__ hashes, float* __restrict__ out) {
    __shared__ __align__(128) float4 zbuf[SLAB_BYTES / 16];   // 64 KB
    __shared__ int s_slab;

    const int t = threadIdx.x;

    // Zero the smem source buffer once (reused for every slab).
    {
        const float4 z = make_float4(0.f, 0.f, 0.f, 0.f);
#pragma unroll
        for (int u = 0; u < (SLAB_BYTES / 16) / THREADS; ++u)   // 8 STS.128
            zbuf[t + u * THREADS] = z;
    }
    // fence: make generic-proxy smem writes visible to the async (TMA) proxy
    asm volatile("fence.proxy.async.shared::cta;" ::: "memory");
    __syncthreads();

    const uint32_t src = (uint32_t)__cvta_generic_to_shared(zbuf);

    for (;;) {
        if (t == 0) s_slab = atomicAdd(&g_ctr, 1);
        __syncthreads();
        const int slab = s_slab;
        if (slab >= NSLAB) break;

        const int m0 = (slab & (SPB - 1)) * MRANGE;
        const int k  = (slab >> 7) % KBLK;
        const int b  = slab / (KBLK * SPB);

        // Hash loads issued early; consumed in the patch phase (L2-resident).
        const int4* hp = (const int4*)(hashes + (b * SS + t) * NH);
        const int4 h0 = __ldg(hp);
        const int4 h1 = __ldg(hp + 1);

        float* const slab_base =
            out + ((long long)(b * KBLK + k) * MB + m0) * SS;

        // ---- bulk store 64KB of zeros, wait for completion --------------
        if (t == 0) {
            asm volatile(
                "cp.async.bulk.global.shared::cta.bulk_group [%0], [%1], %2;\n"
                "cp.async.bulk.commit_group;\n"
                :: "l"(slab_base), "r"(src), "n"(SLAB_BYTES) : "memory");
            asm volatile("cp.async.bulk.wait_group 0;" ::: "memory");
        }
        __syncthreads();   // bulk writes committed before any patch store

        // ---- patch nonzeros from registers ------------------------------
        const int j = t + 2 - k;            // output column for s = t
        if (j >= 0 && j < SS) {
            const int mm[8] = {h0.x & (MB - 1), h0.y & (MB - 1),
                               h0.z & (MB - 1), h0.w & (MB - 1),
                               h1.x & (MB - 1), h1.y & (MB - 1),
                               h1.z & (MB - 1), h1.w & (MB - 1)};
#pragma unroll
            for (int n = 0; n < NH; ++n) {
                const unsigned r = (unsigned)(mm[n] - m0);
                if (r < MRANGE) {
                    int cnt = 0;
#pragma unroll
                    for (int n2 = 0; n2 < NH; ++n2) cnt += (mm[n2] == mm[n]);
                    // duplicate hashes write the same value -> idempotent
                    slab_base[(long long)r * SS + j] = (float)cnt;
                }
            }
        }
        // No barrier needed here: next iteration's bulk store targets a
        // different slab (disjoint addresses), and zbuf is never modified.
    }
}

extern "C" void kernel_launch(void* const* d_in, const int* in_sizes, int n_in,
                              void* d_out, int out_size) {
    const int* hashes = (const int*)d_in[0];
    float* out = (float*)d_out;

    reset_ctr_kernel<<<1, 1>>>();
    bloom_tma_kernel<<<NCTA, THREADS>>>(hashes, out);
}

// round 9
// speedup vs baseline: 1.0155x; 1.0155x over previous
#include <cuda_runtime.h>
#include <cuda_bf16.h>

// Problem constants (fixed by the reference)
#define BB      16
#define SS      512
#define NH      8
#define MB      4096
#define KBLK    5                       // 2*W+1
#define MRANGE  16                      // rows per slab -> 16*2KB = 32KB contiguous
#define SPB     (MB / MRANGE)           // 256 slabs per (b,k) block
#define NSLAB   (BB * KBLK * SPB)       // 20480
#define THREADS 256                     // 8 CTAs/SM resident -> 8 barrier domains

// One CTA per slab = 16 contiguous output rows of one (b,k) block.
// Phase 1: zero the contiguous 32KB slab (8 dependency-free STG.128/thread).
// Phase 2: each thread covers TWO sentence positions (t, t+256) and patches
//          its in-range hashes with counts from 8-way register comparison.
//          __syncthreads() (CTA-scope memory fence) orders phase-1 stores
//          before patch stores; patched lines are L2/MRU-hot.
__global__ void __launch_bounds__(THREADS) bloom_zp_kernel(
        const int* __restrict__ hashes, float* __restrict__ out) {
    const int slab = blockIdx.x;
    const int m0   = (slab & (SPB - 1)) * MRANGE;
    const int k    = (slab >> 8) % KBLK;
    const int b    = slab / (KBLK * SPB);           // slab / 1280
    const int t    = threadIdx.x;

    // Hash loads for both sentence positions, issued before the store burst
    // (input is 256KB total -> fully L2-resident; these are L2 hits).
    const int4* hpA = (const int4*)(hashes + (b * SS + t) * NH);
    const int4 a0 = __ldg(hpA);
    const int4 a1 = __ldg(hpA + 1);
    const int4* hpB = (const int4*)(hashes + (b * SS + t + 256) * NH);
    const int4 b0 = __ldg(hpB);
    const int4 b1 = __ldg(hpB + 1);

    // Slab base: row (b*KBLK + k)*MB + m0, column 0.
    float* const slab_base =
        out + ((long long)(b * KBLK + k) * MB + m0) * SS;

    // ---- Phase 1: zero 2048 float4 = 32KB, contiguous -------------------
    {
        float4* p = (float4*)slab_base + t;
        const float4 z = make_float4(0.f, 0.f, 0.f, 0.f);
#pragma unroll
        for (int u = 0; u < (MRANGE * SS / 4) / THREADS; ++u)   // 8 stores
            p[u * THREADS] = z;          // compile-time imm offsets
    }

    __syncthreads();   // order phase-1 stores before phase-2 patch stores

    // ---- Phase 2: patch nonzeros from registers -------------------------
#pragma unroll
    for (int half = 0; half < 2; ++half) {
        const int s = t + half * 256;          // sentence position
        const int j = s + 2 - k;               // output column
        if (j >= 0 && j < SS) {
            const int4 h0 = half ? b0 : a0;
            const int4 h1 = half ? b1 : a1;
            const int mm[8] = {h0.x & (MB - 1), h0.y & (MB - 1),
                               h0.z & (MB - 1), h0.w & (MB - 1),
                               h1.x & (MB - 1), h1.y & (MB - 1),
                               h1.z & (MB - 1), h1.w & (MB - 1)};
#pragma unroll
            for (int n = 0; n < NH; ++n) {
                const unsigned r = (unsigned)(mm[n] - m0);
                if (r < MRANGE) {
                    int cnt = 0;
#pragma unroll
                    for (int n2 = 0; n2 < NH; ++n2) cnt += (mm[n2] == mm[n]);
                    // duplicate hashes write the same value -> idempotent
                    slab_base[(long long)r * SS + j] = (float)cnt;
                }
            }
        }
    }
}

extern "C" void kernel_launch(void* const* d_in, const int* in_sizes, int n_in,
                              void* d_out, int out_size) {
    const int* hashes = (const int*)d_in[0];
    float* out = (float*)d_out;
    bloom_zp_kernel<<<NSLAB, THREADS>>>(hashes, out);
}